// round 14
// baseline (speedup 1.0000x reference)
// R14 = R13 + pass-major MMA reordering (break the d0,d0,d0 accumulator
// dependency chain that capped tensor pipe at ~32%).
#include <cuda_runtime.h>
#include <cuda_bf16.h>
#include <cstdint>

typedef unsigned int u32;
typedef unsigned long long u64;

#define BATCH 4
#define SEQ   4096
#define HID   512

// ---------------- scratch (no allocations allowed) ----------------
__device__ float g_V[BATCH * SEQ * HID];                    // fp32 V (pre-transpose)
__device__ float g_S[(size_t)BATCH * SEQ * SEQ];            // fp32 scores, 268 MB
__device__ __nv_bfloat16 g_Xh[BATCH * SEQ * HID];           // X hi plane [seq][hid]
__device__ __nv_bfloat16 g_Xl[BATCH * SEQ * HID];
__device__ __nv_bfloat16 g_Qh[BATCH * SEQ * HID];
__device__ __nv_bfloat16 g_Ql[BATCH * SEQ * HID];
__device__ __nv_bfloat16 g_Kh[BATCH * SEQ * HID];
__device__ __nv_bfloat16 g_Kl[BATCH * SEQ * HID];
__device__ __nv_bfloat16 g_Sh[(size_t)BATCH * SEQ * SEQ];   // P hi plane, 134 MB
__device__ __nv_bfloat16 g_Sl[(size_t)BATCH * SEQ * SEQ];   // P lo plane, 134 MB
__device__ __nv_bfloat16 g_WTh[3 * HID * HID];              // W^T hi planes [out][in], QKV stacked
__device__ __nv_bfloat16 g_WTl[3 * HID * HID];
__device__ __nv_bfloat16 g_VTh[BATCH * HID * SEQ];          // V^T hi planes [hid][seq]
__device__ __nv_bfloat16 g_VTl[BATCH * HID * SEQ];

// ---------------- helpers ----------------
__device__ __forceinline__ u32 smem_u32(const void* p) {
    u32 a;
    asm("{ .reg .u64 t; cvta.to.shared.u64 t, %1; cvt.u32.u64 %0, t; }" : "=r"(a) : "l"(p));
    return a;
}

#define SW128(o) ((o) ^ (((o) >> 3) & 0x70))

#define CP16(dst, src) \
    asm volatile("cp.async.cg.shared.global [%0], [%1], 16;" :: "r"(dst), "l"(src) : "memory")
#define CP_COMMIT() asm volatile("cp.async.commit_group;" ::: "memory")
#define CP_WAIT0()  asm volatile("cp.async.wait_group 0;" ::: "memory")

__device__ __forceinline__ u32 pack_bf2(__nv_bfloat16 a, __nv_bfloat16 b) {
    return (u32)__bfloat16_as_ushort(a) | ((u32)__bfloat16_as_ushort(b) << 16);
}

__device__ __forceinline__ void ldm4(u32& r0, u32& r1, u32& r2, u32& r3, u32 addr) {
    asm volatile("ldmatrix.sync.aligned.m8n8.x4.shared.b16 {%0,%1,%2,%3}, [%4];"
                 : "=r"(r0), "=r"(r1), "=r"(r2), "=r"(r3) : "r"(addr));
}

__device__ __forceinline__ void mma_bf16(float* d, const u32* a, u32 b0, u32 b1) {
    asm volatile(
        "mma.sync.aligned.m16n8k16.row.col.f32.bf16.bf16.f32 "
        "{%0,%1,%2,%3}, {%4,%5,%6,%7}, {%8,%9}, {%0,%1,%2,%3};"
        : "+f"(d[0]), "+f"(d[1]), "+f"(d[2]), "+f"(d[3])
        : "r"(a[0]), "r"(a[1]), "r"(a[2]), "r"(a[3]), "r"(b0), "r"(b1));
}

// ---------------- HMMA split-bf16 GEMM (all operands pre-split) ----------------
// D[M,N] = A[M,K] @ B[N,K]^T  fp32-equivalent via 3-pass bf16 split.
// CTA tile 128x256, K-chunk 64 (SW128 128B rows), double-buffered cp.async fills.
// 512 threads = 16 warps in 4(m) x 4(n); warp tile 32x64.
// Inner loop is PASS-MAJOR per np-pair: 8 independent MMAs between reuses of
// any accumulator (hides HMMA result latency).
// Buffer layout (96 KB): A_hi 16K | A_lo 16K | B_hi 32K | B_lo 32K
// EPI: 1 = fp32 * scale, 3 = fp32, 4 = merged-QKV routing
static constexpr int BUF_BYTES = 98304;
static constexpr int TGEMM_SMEM = 1024 + 2 * BUF_BYTES;

template <int EPI>
__global__ __launch_bounds__(512, 1) void tgemm(
    const __nv_bfloat16* __restrict__ Ah, const __nv_bfloat16* __restrict__ Al,
    const __nv_bfloat16* __restrict__ Bh, const __nv_bfloat16* __restrict__ Bl,
    const float* __restrict__ bias,  const float* __restrict__ bias2,
    const float* __restrict__ bias3,
    float* __restrict__ Cf,
    __nv_bfloat16* __restrict__ Ch,  __nv_bfloat16* __restrict__ Cl,
    __nv_bfloat16* __restrict__ C2h, __nv_bfloat16* __restrict__ C2l,
    int Kdim, int lda, int ldb, int ldc,
    long long sA, long long sB, long long sC, float scale)
{
    extern __shared__ char dsm[];

    const int tid = threadIdx.x;
    const long long z = blockIdx.z;
    const int m0 = blockIdx.y * 128, n0 = blockIdx.x * 256;

    const u32 dynb = smem_u32(dsm);
    const u32 pad = (1024u - (dynb & 1023u)) & 1023u;
    const u32 tbu = dynb + pad;

    // ---- cp.async fill: A 2x16KB + B 2x32KB per buffer; 12 x CP16 per thread ----
    const int afr = tid >> 2;               // A row 0..127
    const int acb = (tid & 3) * 32;         // A byte offset in 128B row
    const int bfr = tid >> 1;               // B row 0..255
    const int bcb = (tid & 1) * 64;         // B byte offset in 128B row

    auto fill = [&](int t, int buf) {
        const int k0 = t * 64;
        const u32 base = tbu + (u32)buf * BUF_BYTES;
        {
            const char* ga  = (const char*)(Ah + (size_t)z * sA + (size_t)(m0 + afr) * lda + k0) + acb;
            const char* gal = (const char*)(Al + (size_t)z * sA + (size_t)(m0 + afr) * lda + k0) + acb;
            const u32 so0 = SW128((u32)(afr * 128 + acb));
            const u32 so1 = SW128((u32)(afr * 128 + acb + 16));
            CP16(base + so0, ga);              CP16(base + so1, ga + 16);
            CP16(base + 16384 + so0, gal);     CP16(base + 16384 + so1, gal + 16);
        }
        {
            const char* gb  = (const char*)(Bh + (size_t)z * sB + (size_t)(n0 + bfr) * ldb + k0) + bcb;
            const char* gbl = (const char*)(Bl + (size_t)z * sB + (size_t)(n0 + bfr) * ldb + k0) + bcb;
#pragma unroll
            for (int i = 0; i < 4; ++i) {
                const u32 so = SW128((u32)(bfr * 128 + bcb + i * 16));
                CP16(base + 32768 + so, gb + i * 16);
                CP16(base + 65536 + so, gbl + i * 16);
            }
        }
    };

    // ---- warp / lane geometry: 16 warps as 4(m) x 4(n), warp tile 32x64 ----
    const int lane = tid & 31;
    const int w = tid >> 5;
    const int wm = (w & 3) * 32;
    const int wn = (w >> 2) * 64;
    const int arow = (((lane >> 3) & 1) << 3) + (lane & 7);   // A: m within 16x16 tile
    const int akof = (lane >> 4) << 3;                        // A: k offset
    const int brow = ((lane >> 4) << 3) + (lane & 7);         // B: n within 16-col pair
    const int bkof = ((lane >> 3) & 1) << 3;                  // B: k offset

    float acc[2][8][4];
#pragma unroll
    for (int mt = 0; mt < 2; ++mt)
#pragma unroll
        for (int nt = 0; nt < 8; ++nt)
#pragma unroll
            for (int i = 0; i < 4; ++i) acc[mt][nt][i] = 0.f;

    auto compute = [&](int buf) {
        const u32 a_hi = tbu + (u32)buf * BUF_BYTES;
        const u32 a_lo = a_hi + 16384;
        const u32 b_hi = a_hi + 32768;
        const u32 b_lo = a_hi + 65536;
#pragma unroll
        for (int ks = 0; ks < 4; ++ks) {
            const int kk = ks * 16;
            u32 Ahf[2][4], Alf[2][4];
#pragma unroll
            for (int mt = 0; mt < 2; ++mt) {
                const u32 off = SW128((u32)((wm + mt * 16 + arow) * 128 + (kk + akof) * 2));
                ldm4(Ahf[mt][0], Ahf[mt][1], Ahf[mt][2], Ahf[mt][3], a_hi + off);
                ldm4(Alf[mt][0], Alf[mt][1], Alf[mt][2], Alf[mt][3], a_lo + off);
            }
#pragma unroll
            for (int npp = 0; npp < 2; ++npp) {
                u32 BH[2][4], BL[2][4];
#pragma unroll
                for (int j = 0; j < 2; ++j) {
                    const int np = npp * 2 + j;
                    const u32 off = SW128((u32)((wn + np * 16 + brow) * 128 + (kk + bkof) * 2));
                    ldm4(BH[j][0], BH[j][1], BH[j][2], BH[j][3], b_hi + off);
                    ldm4(BL[j][0], BL[j][1], BL[j][2], BL[j][3], b_lo + off);
                }
                // pass 1: A_hi * B_hi  (8 independent MMAs)
#pragma unroll
                for (int j = 0; j < 2; ++j) {
                    const int np = npp * 2 + j;
#pragma unroll
                    for (int mt = 0; mt < 2; ++mt) {
                        mma_bf16(acc[mt][np * 2 + 0], Ahf[mt], BH[j][0], BH[j][1]);
                        mma_bf16(acc[mt][np * 2 + 1], Ahf[mt], BH[j][2], BH[j][3]);
                    }
                }
                // pass 2: A_hi * B_lo
#pragma unroll
                for (int j = 0; j < 2; ++j) {
                    const int np = npp * 2 + j;
#pragma unroll
                    for (int mt = 0; mt < 2; ++mt) {
                        mma_bf16(acc[mt][np * 2 + 0], Ahf[mt], BL[j][0], BL[j][1]);
                        mma_bf16(acc[mt][np * 2 + 1], Ahf[mt], BL[j][2], BL[j][3]);
                    }
                }
                // pass 3: A_lo * B_hi
#pragma unroll
                for (int j = 0; j < 2; ++j) {
                    const int np = npp * 2 + j;
#pragma unroll
                    for (int mt = 0; mt < 2; ++mt) {
                        mma_bf16(acc[mt][np * 2 + 0], Alf[mt], BH[j][0], BH[j][1]);
                        mma_bf16(acc[mt][np * 2 + 1], Alf[mt], BH[j][2], BH[j][3]);
                    }
                }
            }
        }
    };

    fill(0, 0);
    CP_COMMIT();
    CP_WAIT0();
    __syncthreads();

    const int nT = Kdim >> 6;
    int cur = 0;
    for (int t = 0; t < nT; ++t) {
        if (t + 1 < nT) { fill(t + 1, cur ^ 1); CP_COMMIT(); }
        compute(cur);
        if (t + 1 < nT) CP_WAIT0();
        __syncthreads();
        cur ^= 1;
    }

    // ---- epilogue: registers -> global ----
#pragma unroll
    for (int mt = 0; mt < 2; ++mt) {
#pragma unroll
        for (int nt = 0; nt < 8; ++nt) {
            const int mr = m0 + wm + mt * 16 + (lane >> 2);
            const int nc = n0 + wn + nt * 8 + (lane & 3) * 2;
            float v0 = acc[mt][nt][0], v1 = acc[mt][nt][1];
            float v2 = acc[mt][nt][2], v3 = acc[mt][nt][3];
            if (EPI == 1) { v0 *= scale; v1 *= scale; v2 *= scale; v3 *= scale; }
            if (EPI == 1 || EPI == 3) {
                float* c0 = Cf + (size_t)z * sC + (size_t)mr * ldc + nc;
                float* c1 = Cf + (size_t)z * sC + (size_t)(mr + 8) * ldc + nc;
                *(float2*)c0 = make_float2(v0, v1);
                *(float2*)c1 = make_float2(v2, v3);
            }
            if (EPI == 4) {
                const int nloc = nc & 511;
                const float* bp = (nc < 512) ? bias : (nc < 1024) ? bias2 : bias3;
                const float b0 = bp[nloc], b1 = bp[nloc + 1];
                v0 += b0; v1 += b1; v2 += b0; v3 += b1;
                const size_t o0 = (size_t)mr * HID + nloc;
                const size_t o1 = (size_t)(mr + 8) * HID + nloc;
                if (nc < 1024) {
                    __nv_bfloat16* ph = (nc < 512) ? Ch : C2h;
                    __nv_bfloat16* pl = (nc < 512) ? Cl : C2l;
                    __nv_bfloat16 h0 = __float2bfloat16_rn(v0);
                    __nv_bfloat16 h1 = __float2bfloat16_rn(v1);
                    __nv_bfloat16 h2 = __float2bfloat16_rn(v2);
                    __nv_bfloat16 h3 = __float2bfloat16_rn(v3);
                    *(u32*)(ph + o0) = pack_bf2(h0, h1);
                    *(u32*)(ph + o1) = pack_bf2(h2, h3);
                    *(u32*)(pl + o0) = pack_bf2(__float2bfloat16_rn(v0 - __bfloat162float(h0)),
                                                __float2bfloat16_rn(v1 - __bfloat162float(h1)));
                    *(u32*)(pl + o1) = pack_bf2(__float2bfloat16_rn(v2 - __bfloat162float(h2)),
                                                __float2bfloat16_rn(v3 - __bfloat162float(h3)));
                } else {
                    *(float2*)(Cf + o0) = make_float2(v0, v1);
                    *(float2*)(Cf + o1) = make_float2(v2, v3);
                }
            }
        }
    }
}

// ---------------- elementwise bf16 split: X -> Xh, Xl ----------------
__global__ __launch_bounds__(256) void split_k(
    const float* __restrict__ in, __nv_bfloat16* __restrict__ oh,
    __nv_bfloat16* __restrict__ ol)
{
    const size_t i = ((size_t)blockIdx.x * 256 + threadIdx.x) * 4;
    float4 v = *(const float4*)(in + i);
    __nv_bfloat16 h0 = __float2bfloat16_rn(v.x);
    __nv_bfloat16 h1 = __float2bfloat16_rn(v.y);
    __nv_bfloat16 h2 = __float2bfloat16_rn(v.z);
    __nv_bfloat16 h3 = __float2bfloat16_rn(v.w);
    uint2 hp, lp;
    hp.x = pack_bf2(h0, h1);
    hp.y = pack_bf2(h2, h3);
    lp.x = pack_bf2(__float2bfloat16_rn(v.x - __bfloat162float(h0)),
                    __float2bfloat16_rn(v.y - __bfloat162float(h1)));
    lp.y = pack_bf2(__float2bfloat16_rn(v.z - __bfloat162float(h2)),
                    __float2bfloat16_rn(v.w - __bfloat162float(h3)));
    *(uint2*)(oh + i) = hp;
    *(uint2*)(ol + i) = lp;
}

// ---------------- transpose + bf16 split: out[c][r] = split(in[r][c]) ----------------
__global__ __launch_bounds__(256) void transpose_split_k(
    const float* __restrict__ in, __nv_bfloat16* __restrict__ oh,
    __nv_bfloat16* __restrict__ ol, int R, int C,
    long long sIn, long long sOut)
{
    __shared__ float tile[32][33];
    const long long z = blockIdx.z;
    in += z * sIn; oh += z * sOut; ol += z * sOut;
    const int c0 = blockIdx.x * 32, r0 = blockIdx.y * 32;
    const int tx = threadIdx.x, ty = threadIdx.y;
#pragma unroll
    for (int j = 0; j < 32; j += 8)
        tile[ty + j][tx] = in[(size_t)(r0 + ty + j) * C + c0 + tx];
    __syncthreads();
#pragma unroll
    for (int j = 0; j < 32; j += 8) {
        float f = tile[tx][ty + j];
        __nv_bfloat16 h = __float2bfloat16_rn(f);
        __nv_bfloat16 l = __float2bfloat16_rn(f - __bfloat162float(h));
        size_t o = (size_t)(c0 + ty + j) * R + r0 + tx;
        oh[o] = h;
        ol[o] = l;
    }
}

// ---------------- row softmax over 4096 cols, output split bf16 planes ----------------
__global__ __launch_bounds__(256) void softmax_split_k(
    const float* __restrict__ S, __nv_bfloat16* __restrict__ Ph,
    __nv_bfloat16* __restrict__ Pl)
{
    const size_t row = blockIdx.x;
    const float4* p = reinterpret_cast<const float4*>(S + (row << 12));
    uint2* oh = reinterpret_cast<uint2*>(Ph + (row << 12));
    uint2* ol = reinterpret_cast<uint2*>(Pl + (row << 12));
    const int tid = threadIdx.x;

    float4 v[4];
#pragma unroll
    for (int r = 0; r < 4; ++r) v[r] = p[tid + (r << 8)];

    float m = v[0].x;
#pragma unroll
    for (int r = 0; r < 4; ++r) {
        m = fmaxf(m, v[r].x); m = fmaxf(m, v[r].y);
        m = fmaxf(m, v[r].z); m = fmaxf(m, v[r].w);
    }
#pragma unroll
    for (int o = 16; o > 0; o >>= 1) m = fmaxf(m, __shfl_xor_sync(0xffffffffu, m, o));

    __shared__ float red[8];
    if ((tid & 31) == 0) red[tid >> 5] = m;
    __syncthreads();
    m = red[0];
#pragma unroll
    for (int i = 1; i < 8; ++i) m = fmaxf(m, red[i]);
    __syncthreads();

    float s = 0.f;
#pragma unroll
    for (int r = 0; r < 4; ++r) {
        v[r].x = __expf(v[r].x - m); s += v[r].x;
        v[r].y = __expf(v[r].y - m); s += v[r].y;
        v[r].z = __expf(v[r].z - m); s += v[r].z;
        v[r].w = __expf(v[r].w - m); s += v[r].w;
    }
#pragma unroll
    for (int o = 16; o > 0; o >>= 1) s += __shfl_xor_sync(0xffffffffu, s, o);
    if ((tid & 31) == 0) red[tid >> 5] = s;
    __syncthreads();
    s = 0.f;
#pragma unroll
    for (int i = 0; i < 8; ++i) s += red[i];

    const float inv = 1.0f / s;
#pragma unroll
    for (int r = 0; r < 4; ++r) {
        float f0 = v[r].x * inv, f1 = v[r].y * inv;
        float f2 = v[r].z * inv, f3 = v[r].w * inv;
        __nv_bfloat16 h0 = __float2bfloat16_rn(f0);
        __nv_bfloat16 h1 = __float2bfloat16_rn(f1);
        __nv_bfloat16 h2 = __float2bfloat16_rn(f2);
        __nv_bfloat16 h3 = __float2bfloat16_rn(f3);
        uint2 hp, lp;
        hp.x = pack_bf2(h0, h1);
        hp.y = pack_bf2(h2, h3);
        lp.x = pack_bf2(__float2bfloat16_rn(f0 - __bfloat162float(h0)),
                        __float2bfloat16_rn(f1 - __bfloat162float(h1)));
        lp.y = pack_bf2(__float2bfloat16_rn(f2 - __bfloat162float(h2)),
                        __float2bfloat16_rn(f3 - __bfloat162float(h3)));
        oh[tid + (r << 8)] = hp;
        ol[tid + (r << 8)] = lp;
    }
}

// ---------------- launch ----------------
extern "C" void kernel_launch(void* const* d_in, const int* in_sizes, int n_in,
                              void* d_out, int out_size)
{
    (void)in_sizes; (void)n_in; (void)out_size;
    const float* X  = (const float*)d_in[0];
    const float* Wq = (const float*)d_in[1];
    const float* bq = (const float*)d_in[2];
    const float* Wk = (const float*)d_in[3];
    const float* bk = (const float*)d_in[4];
    const float* Wv = (const float*)d_in[5];
    const float* bv = (const float*)d_in[6];
    float* out = (float*)d_out;

    float *Vp, *Sp;
    __nv_bfloat16 *Xh, *Xl, *Qh, *Ql, *Kh, *Kl, *Sh, *Sl, *WTh, *WTl, *VTh, *VTl;
    cudaGetSymbolAddress((void**)&Vp,  g_V);
    cudaGetSymbolAddress((void**)&Sp,  g_S);
    cudaGetSymbolAddress((void**)&Xh,  g_Xh);
    cudaGetSymbolAddress((void**)&Xl,  g_Xl);
    cudaGetSymbolAddress((void**)&Qh,  g_Qh);
    cudaGetSymbolAddress((void**)&Ql,  g_Ql);
    cudaGetSymbolAddress((void**)&Kh,  g_Kh);
    cudaGetSymbolAddress((void**)&Kl,  g_Kl);
    cudaGetSymbolAddress((void**)&Sh,  g_Sh);
    cudaGetSymbolAddress((void**)&Sl,  g_Sl);
    cudaGetSymbolAddress((void**)&WTh, g_WTh);
    cudaGetSymbolAddress((void**)&WTl, g_WTl);
    cudaGetSymbolAddress((void**)&VTh, g_VTh);
    cudaGetSymbolAddress((void**)&VTl, g_VTl);

    cudaFuncSetAttribute(tgemm<1>, cudaFuncAttributeMaxDynamicSharedMemorySize, TGEMM_SMEM);
    cudaFuncSetAttribute(tgemm<3>, cudaFuncAttributeMaxDynamicSharedMemorySize, TGEMM_SMEM);
    cudaFuncSetAttribute(tgemm<4>, cudaFuncAttributeMaxDynamicSharedMemorySize, TGEMM_SMEM);

    const float scale = 0.04419417382415922f;  // 1/sqrt(512)
    dim3 gblk(512);
    dim3 tblk(32, 8);

    // 1a) split X into bf16 hi/lo planes
    split_k<<<(BATCH * SEQ * HID) / (256 * 4), 256>>>(X, Xh, Xl);

    // 1b) transpose+split weights: W[in][out] -> plane[out][in], QKV stacked
    dim3 gtw(HID / 32, HID / 32, 1);
    transpose_split_k<<<gtw, tblk>>>(Wq, WTh + 0 * HID * HID, WTl + 0 * HID * HID, HID, HID, 0, 0);
    transpose_split_k<<<gtw, tblk>>>(Wk, WTh + 1 * HID * HID, WTl + 1 * HID * HID, HID, HID, 0, 0);
    transpose_split_k<<<gtw, tblk>>>(Wv, WTh + 2 * HID * HID, WTl + 2 * HID * HID, HID, HID, 0, 0);

    // 2) merged QKV projection: M=16384, N=1536, K=512
    dim3 g1((3 * HID) / 256, (BATCH * SEQ) / 128, 1);
    tgemm<4><<<g1, gblk, TGEMM_SMEM>>>(
        Xh, Xl, WTh, WTl, bq, bk, bv,
        Vp, Qh, Ql, Kh, Kl,
        HID, HID, HID, HID, 0, 0, 0, 1.f);

    // 3) transpose+split V: [seq][hid] -> plane[hid][seq], per batch
    dim3 gtv(HID / 32, SEQ / 32, BATCH);
    transpose_split_k<<<gtv, tblk>>>(Vp, VTh, VTl, SEQ, HID,
                                     (long long)SEQ * HID, (long long)HID * SEQ);

    // 4) scores = scale * Q @ K^T
    dim3 g2(SEQ / 256, SEQ / 128, BATCH);
    tgemm<1><<<g2, gblk, TGEMM_SMEM>>>(
        Qh, Ql, Kh, Kl, nullptr, nullptr, nullptr,
        Sp, nullptr, nullptr, nullptr, nullptr,
        HID, HID, HID, SEQ,
        (long long)SEQ * HID, (long long)SEQ * HID, (long long)SEQ * SEQ, scale);

    // 5) softmax -> split bf16 planes
    softmax_split_k<<<BATCH * SEQ, 256>>>(Sp, Sh, Sl);

    // 6) out = P @ V
    dim3 g3(HID / 256, SEQ / 128, BATCH);
    tgemm<3><<<g3, gblk, TGEMM_SMEM>>>(
        Sh, Sl, VTh, VTl, nullptr, nullptr, nullptr,
        out, nullptr, nullptr, nullptr, nullptr,
        SEQ, SEQ, SEQ, HID,
        (long long)SEQ * SEQ, (long long)HID * SEQ, (long long)SEQ * HID, 1.f);
}

// round 15
// speedup vs baseline: 1.3329x; 1.3329x over previous
// R15 = fp16 asymmetric 2-pass split: C = A_hi@B_hi + A_hi@B_lo.
// A-side (X, Q, P) stores hi plane only; B-side (W, K, V) stores hi+lo.
// Work -33% vs 3-pass bf16; predicted rel_err ~1e-4 (<1e-3).
#include <cuda_runtime.h>
#include <cuda_fp16.h>
#include <cstdint>

typedef unsigned int u32;
typedef unsigned long long u64;

#define BATCH 4
#define SEQ   4096
#define HID   512

// ---------------- scratch (no allocations allowed) ----------------
__device__ float g_V[BATCH * SEQ * HID];                    // fp32 V (pre-transpose)
__device__ float g_S[(size_t)BATCH * SEQ * SEQ];            // fp32 scores, 268 MB
__device__ __half g_Xh[BATCH * SEQ * HID];                  // X hi plane [seq][hid]
__device__ __half g_Qh[BATCH * SEQ * HID];                  // Q hi plane (A-side: hi only)
__device__ __half g_Kh[BATCH * SEQ * HID];                  // K hi plane
__device__ __half g_Kl[BATCH * SEQ * HID];                  // K lo plane
__device__ __half g_Ph[(size_t)BATCH * SEQ * SEQ];          // P hi plane, 134 MB (A-side)
__device__ __half g_WTh[3 * HID * HID];                     // W^T hi planes [out][in], QKV stacked
__device__ __half g_WTl[3 * HID * HID];
__device__ __half g_VTh[BATCH * HID * SEQ];                 // V^T hi planes [hid][seq]
__device__ __half g_VTl[BATCH * HID * SEQ];

// ---------------- helpers ----------------
__device__ __forceinline__ u32 smem_u32(const void* p) {
    u32 a;
    asm("{ .reg .u64 t; cvta.to.shared.u64 t, %1; cvt.u32.u64 %0, t; }" : "=r"(a) : "l"(p));
    return a;
}

#define SW128(o) ((o) ^ (((o) >> 3) & 0x70))

#define CP16(dst, src) \
    asm volatile("cp.async.cg.shared.global [%0], [%1], 16;" :: "r"(dst), "l"(src) : "memory")
#define CP_COMMIT() asm volatile("cp.async.commit_group;" ::: "memory")
#define CP_WAIT0()  asm volatile("cp.async.wait_group 0;" ::: "memory")

__device__ __forceinline__ u32 pack_h2(__half a, __half b) {
    return (u32)__half_as_ushort(a) | ((u32)__half_as_ushort(b) << 16);
}

__device__ __forceinline__ void ldm4(u32& r0, u32& r1, u32& r2, u32& r3, u32 addr) {
    asm volatile("ldmatrix.sync.aligned.m8n8.x4.shared.b16 {%0,%1,%2,%3}, [%4];"
                 : "=r"(r0), "=r"(r1), "=r"(r2), "=r"(r3) : "r"(addr));
}

__device__ __forceinline__ void mma_f16(float* d, const u32* a, u32 b0, u32 b1) {
    asm volatile(
        "mma.sync.aligned.m16n8k16.row.col.f32.f16.f16.f32 "
        "{%0,%1,%2,%3}, {%4,%5,%6,%7}, {%8,%9}, {%0,%1,%2,%3};"
        : "+f"(d[0]), "+f"(d[1]), "+f"(d[2]), "+f"(d[3])
        : "r"(a[0]), "r"(a[1]), "r"(a[2]), "r"(a[3]), "r"(b0), "r"(b1));
}

// ---------------- HMMA fp16 2-pass GEMM ----------------
// D[M,N] = A[M,K] @ B[N,K]^T, fp16 asymmetric split:
//   C = A_hi @ B_hi + A_hi @ B_lo   (dropped (A-A_hi)@B term ~ 2^-13 rel)
// CTA tile 128x256, K-chunk 64 (SW128 128B rows), double-buffered cp.async.
// 512 threads = 16 warps in 4(m) x 4(n); warp tile 32x64.
// Buffer (80 KB): A_hi 16K | B_hi 32K | B_lo 32K
// EPI: 1 = fp32 * scale, 3 = fp32, 4 = merged-QKV (Q hi-only+bias, K hi/lo+bias, V fp32+bias)
static constexpr int BUF_BYTES = 81920;
static constexpr int TGEMM_SMEM = 1024 + 2 * BUF_BYTES;   // 164 KB

template <int EPI>
__global__ __launch_bounds__(512, 1) void tgemm(
    const __half* __restrict__ Ah,
    const __half* __restrict__ Bh, const __half* __restrict__ Bl,
    const float* __restrict__ bias,  const float* __restrict__ bias2,
    const float* __restrict__ bias3,
    float* __restrict__ Cf,
    __half* __restrict__ Cqh,                 // EPI4: Q hi plane
    __half* __restrict__ Ckh, __half* __restrict__ Ckl,   // EPI4: K hi/lo planes
    int Kdim, int lda, int ldb, int ldc,
    long long sA, long long sB, long long sC, float scale)
{
    extern __shared__ char dsm[];

    const int tid = threadIdx.x;
    const long long z = blockIdx.z;
    const int m0 = blockIdx.y * 128, n0 = blockIdx.x * 256;

    const u32 dynb = smem_u32(dsm);
    const u32 pad = (1024u - (dynb & 1023u)) & 1023u;
    const u32 tbu = dynb + pad;

    // ---- cp.async fill: A_hi 16KB + B_hi 32KB + B_lo 32KB; 10 x CP16/thread ----
    const int afr = tid >> 2;               // A row 0..127
    const int acb = (tid & 3) * 32;         // A byte offset in 128B row
    const int bfr = tid >> 1;               // B row 0..255
    const int bcb = (tid & 1) * 64;         // B byte offset in 128B row

    auto fill = [&](int t, int buf) {
        const int k0 = t * 64;
        const u32 base = tbu + (u32)buf * BUF_BYTES;
        {
            const char* ga = (const char*)(Ah + (size_t)z * sA + (size_t)(m0 + afr) * lda + k0) + acb;
            const u32 so0 = SW128((u32)(afr * 128 + acb));
            const u32 so1 = SW128((u32)(afr * 128 + acb + 16));
            CP16(base + so0, ga);
            CP16(base + so1, ga + 16);
        }
        {
            const char* gb  = (const char*)(Bh + (size_t)z * sB + (size_t)(n0 + bfr) * ldb + k0) + bcb;
            const char* gbl = (const char*)(Bl + (size_t)z * sB + (size_t)(n0 + bfr) * ldb + k0) + bcb;
#pragma unroll
            for (int i = 0; i < 4; ++i) {
                const u32 so = SW128((u32)(bfr * 128 + bcb + i * 16));
                CP16(base + 16384 + so, gb + i * 16);
                CP16(base + 49152 + so, gbl + i * 16);
            }
        }
    };

    // ---- warp / lane geometry: 16 warps as 4(m) x 4(n), warp tile 32x64 ----
    const int lane = tid & 31;
    const int w = tid >> 5;
    const int wm = (w & 3) * 32;
    const int wn = (w >> 2) * 64;
    const int arow = (((lane >> 3) & 1) << 3) + (lane & 7);   // A: m within 16x16 tile
    const int akof = (lane >> 4) << 3;                        // A: k offset
    const int brow = ((lane >> 4) << 3) + (lane & 7);         // B: n within 16-col pair
    const int bkof = ((lane >> 3) & 1) << 3;                  // B: k offset

    float acc[2][8][4];
#pragma unroll
    for (int mt = 0; mt < 2; ++mt)
#pragma unroll
        for (int nt = 0; nt < 8; ++nt)
#pragma unroll
            for (int i = 0; i < 4; ++i) acc[mt][nt][i] = 0.f;

    auto compute = [&](int buf) {
        const u32 a_hi = tbu + (u32)buf * BUF_BYTES;
        const u32 b_hi = a_hi + 16384;
        const u32 b_lo = a_hi + 49152;
#pragma unroll
        for (int ks = 0; ks < 4; ++ks) {
            const int kk = ks * 16;
            u32 Ahf[2][4];
#pragma unroll
            for (int mt = 0; mt < 2; ++mt) {
                const u32 off = SW128((u32)((wm + mt * 16 + arow) * 128 + (kk + akof) * 2));
                ldm4(Ahf[mt][0], Ahf[mt][1], Ahf[mt][2], Ahf[mt][3], a_hi + off);
            }
#pragma unroll
            for (int npp = 0; npp < 2; ++npp) {
                u32 BH[2][4], BL[2][4];
#pragma unroll
                for (int j = 0; j < 2; ++j) {
                    const int np = npp * 2 + j;
                    const u32 off = SW128((u32)((wn + np * 16 + brow) * 128 + (kk + bkof) * 2));
                    ldm4(BH[j][0], BH[j][1], BH[j][2], BH[j][3], b_hi + off);
                    ldm4(BL[j][0], BL[j][1], BL[j][2], BL[j][3], b_lo + off);
                }
                // pass 1: A_hi * B_hi  (8 independent MMAs)
#pragma unroll
                for (int j = 0; j < 2; ++j) {
                    const int np = npp * 2 + j;
#pragma unroll
                    for (int mt = 0; mt < 2; ++mt) {
                        mma_f16(acc[mt][np * 2 + 0], Ahf[mt], BH[j][0], BH[j][1]);
                        mma_f16(acc[mt][np * 2 + 1], Ahf[mt], BH[j][2], BH[j][3]);
                    }
                }
                // pass 2: A_hi * B_lo
#pragma unroll
                for (int j = 0; j < 2; ++j) {
                    const int np = npp * 2 + j;
#pragma unroll
                    for (int mt = 0; mt < 2; ++mt) {
                        mma_f16(acc[mt][np * 2 + 0], Ahf[mt], BL[j][0], BL[j][1]);
                        mma_f16(acc[mt][np * 2 + 1], Ahf[mt], BL[j][2], BL[j][3]);
                    }
                }
            }
        }
    };

    fill(0, 0);
    CP_COMMIT();
    CP_WAIT0();
    __syncthreads();

    const int nT = Kdim >> 6;
    int cur = 0;
    for (int t = 0; t < nT; ++t) {
        if (t + 1 < nT) { fill(t + 1, cur ^ 1); CP_COMMIT(); }
        compute(cur);
        if (t + 1 < nT) CP_WAIT0();
        __syncthreads();
        cur ^= 1;
    }

    // ---- epilogue: registers -> global ----
#pragma unroll
    for (int mt = 0; mt < 2; ++mt) {
#pragma unroll
        for (int nt = 0; nt < 8; ++nt) {
            const int mr = m0 + wm + mt * 16 + (lane >> 2);
            const int nc = n0 + wn + nt * 8 + (lane & 3) * 2;
            float v0 = acc[mt][nt][0], v1 = acc[mt][nt][1];
            float v2 = acc[mt][nt][2], v3 = acc[mt][nt][3];
            if (EPI == 1) { v0 *= scale; v1 *= scale; v2 *= scale; v3 *= scale; }
            if (EPI == 1 || EPI == 3) {
                float* c0 = Cf + (size_t)z * sC + (size_t)mr * ldc + nc;
                float* c1 = Cf + (size_t)z * sC + (size_t)(mr + 8) * ldc + nc;
                *(float2*)c0 = make_float2(v0, v1);
                *(float2*)c1 = make_float2(v2, v3);
            }
            if (EPI == 4) {
                const int nloc = nc & 511;
                const float* bp = (nc < 512) ? bias : (nc < 1024) ? bias2 : bias3;
                const float b0 = bp[nloc], b1 = bp[nloc + 1];
                v0 += b0; v1 += b1; v2 += b0; v3 += b1;
                const size_t o0 = (size_t)mr * HID + nloc;
                const size_t o1 = (size_t)(mr + 8) * HID + nloc;
                if (nc < 512) {
                    // Q: hi plane only (A-side operand of scores GEMM)
                    *(u32*)(Cqh + o0) = pack_h2(__float2half_rn(v0), __float2half_rn(v1));
                    *(u32*)(Cqh + o1) = pack_h2(__float2half_rn(v2), __float2half_rn(v3));
                } else if (nc < 1024) {
                    // K: hi + lo planes (B-side operand)
                    __half h0 = __float2half_rn(v0);
                    __half h1 = __float2half_rn(v1);
                    __half h2 = __float2half_rn(v2);
                    __half h3 = __float2half_rn(v3);
                    *(u32*)(Ckh + o0) = pack_h2(h0, h1);
                    *(u32*)(Ckh + o1) = pack_h2(h2, h3);
                    *(u32*)(Ckl + o0) = pack_h2(__float2half_rn(v0 - __half2float(h0)),
                                                __float2half_rn(v1 - __half2float(h1)));
                    *(u32*)(Ckl + o1) = pack_h2(__float2half_rn(v2 - __half2float(h2)),
                                                __float2half_rn(v3 - __half2float(h3)));
                } else {
                    *(float2*)(Cf + o0) = make_float2(v0, v1);
                    *(float2*)(Cf + o1) = make_float2(v2, v3);
                }
            }
        }
    }
}

// ---------------- elementwise fp16 hi: X -> Xh ----------------
__global__ __launch_bounds__(256) void split_hi_k(
    const float* __restrict__ in, __half* __restrict__ oh)
{
    const size_t i = ((size_t)blockIdx.x * 256 + threadIdx.x) * 4;
    float4 v = *(const float4*)(in + i);
    uint2 hp;
    hp.x = pack_h2(__float2half_rn(v.x), __float2half_rn(v.y));
    hp.y = pack_h2(__float2half_rn(v.z), __float2half_rn(v.w));
    *(uint2*)(oh + i) = hp;
}

// ---------------- transpose + fp16 split: out[c][r] = split(in[r][c]) ----------------
__global__ __launch_bounds__(256) void transpose_split_k(
    const float* __restrict__ in, __half* __restrict__ oh,
    __half* __restrict__ ol, int R, int C,
    long long sIn, long long sOut)
{
    __shared__ float tile[32][33];
    const long long z = blockIdx.z;
    in += z * sIn; oh += z * sOut; ol += z * sOut;
    const int c0 = blockIdx.x * 32, r0 = blockIdx.y * 32;
    const int tx = threadIdx.x, ty = threadIdx.y;
#pragma unroll
    for (int j = 0; j < 32; j += 8)
        tile[ty + j][tx] = in[(size_t)(r0 + ty + j) * C + c0 + tx];
    __syncthreads();
#pragma unroll
    for (int j = 0; j < 32; j += 8) {
        float f = tile[tx][ty + j];
        __half h = __float2half_rn(f);
        __half l = __float2half_rn(f - __half2float(h));
        size_t o = (size_t)(c0 + ty + j) * R + r0 + tx;
        oh[o] = h;
        ol[o] = l;
    }
}

// ---------------- row softmax over 4096 cols, output fp16 hi plane ----------------
__global__ __launch_bounds__(256) void softmax_hi_k(
    const float* __restrict__ S, __half* __restrict__ Ph)
{
    const size_t row = blockIdx.x;
    const float4* p = reinterpret_cast<const float4*>(S + (row << 12));
    uint2* oh = reinterpret_cast<uint2*>(Ph + (row << 12));
    const int tid = threadIdx.x;

    float4 v[4];
#pragma unroll
    for (int r = 0; r < 4; ++r) v[r] = p[tid + (r << 8)];

    float m = v[0].x;
#pragma unroll
    for (int r = 0; r < 4; ++r) {
        m = fmaxf(m, v[r].x); m = fmaxf(m, v[r].y);
        m = fmaxf(m, v[r].z); m = fmaxf(m, v[r].w);
    }
#pragma unroll
    for (int o = 16; o > 0; o >>= 1) m = fmaxf(m, __shfl_xor_sync(0xffffffffu, m, o));

    __shared__ float red[8];
    if ((tid & 31) == 0) red[tid >> 5] = m;
    __syncthreads();
    m = red[0];
#pragma unroll
    for (int i = 1; i < 8; ++i) m = fmaxf(m, red[i]);
    __syncthreads();

    float s = 0.f;
#pragma unroll
    for (int r = 0; r < 4; ++r) {
        v[r].x = __expf(v[r].x - m); s += v[r].x;
        v[r].y = __expf(v[r].y - m); s += v[r].y;
        v[r].z = __expf(v[r].z - m); s += v[r].z;
        v[r].w = __expf(v[r].w - m); s += v[r].w;
    }
#pragma unroll
    for (int o = 16; o > 0; o >>= 1) s += __shfl_xor_sync(0xffffffffu, s, o);
    if ((tid & 31) == 0) red[tid >> 5] = s;
    __syncthreads();
    s = 0.f;
#pragma unroll
    for (int i = 0; i < 8; ++i) s += red[i];

    const float inv = 1.0f / s;
#pragma unroll
    for (int r = 0; r < 4; ++r) {
        uint2 hp;
        hp.x = pack_h2(__float2half_rn(v[r].x * inv), __float2half_rn(v[r].y * inv));
        hp.y = pack_h2(__float2half_rn(v[r].z * inv), __float2half_rn(v[r].w * inv));
        oh[tid + (r << 8)] = hp;
    }
}

// ---------------- launch ----------------
extern "C" void kernel_launch(void* const* d_in, const int* in_sizes, int n_in,
                              void* d_out, int out_size)
{
    (void)in_sizes; (void)n_in; (void)out_size;
    const float* X  = (const float*)d_in[0];
    const float* Wq = (const float*)d_in[1];
    const float* bq = (const float*)d_in[2];
    const float* Wk = (const float*)d_in[3];
    const float* bk = (const float*)d_in[4];
    const float* Wv = (const float*)d_in[5];
    const float* bv = (const float*)d_in[6];
    float* out = (float*)d_out;

    float *Vp, *Sp;
    __half *Xh, *Qh, *Kh, *Kl, *Ph, *WTh, *WTl, *VTh, *VTl;
    cudaGetSymbolAddress((void**)&Vp,  g_V);
    cudaGetSymbolAddress((void**)&Sp,  g_S);
    cudaGetSymbolAddress((void**)&Xh,  g_Xh);
    cudaGetSymbolAddress((void**)&Qh,  g_Qh);
    cudaGetSymbolAddress((void**)&Kh,  g_Kh);
    cudaGetSymbolAddress((void**)&Kl,  g_Kl);
    cudaGetSymbolAddress((void**)&Ph,  g_Ph);
    cudaGetSymbolAddress((void**)&WTh, g_WTh);
    cudaGetSymbolAddress((void**)&WTl, g_WTl);
    cudaGetSymbolAddress((void**)&VTh, g_VTh);
    cudaGetSymbolAddress((void**)&VTl, g_VTl);

    cudaFuncSetAttribute(tgemm<1>, cudaFuncAttributeMaxDynamicSharedMemorySize, TGEMM_SMEM);
    cudaFuncSetAttribute(tgemm<3>, cudaFuncAttributeMaxDynamicSharedMemorySize, TGEMM_SMEM);
    cudaFuncSetAttribute(tgemm<4>, cudaFuncAttributeMaxDynamicSharedMemorySize, TGEMM_SMEM);

    const float scale = 0.04419417382415922f;  // 1/sqrt(512)
    dim3 gblk(512);
    dim3 tblk(32, 8);

    // 1a) X -> fp16 hi plane only (A-side)
    split_hi_k<<<(BATCH * SEQ * HID) / (256 * 4), 256>>>(X, Xh);

    // 1b) transpose+split weights: W[in][out] -> plane[out][in], QKV stacked
    dim3 gtw(HID / 32, HID / 32, 1);
    transpose_split_k<<<gtw, tblk>>>(Wq, WTh + 0 * HID * HID, WTl + 0 * HID * HID, HID, HID, 0, 0);
    transpose_split_k<<<gtw, tblk>>>(Wk, WTh + 1 * HID * HID, WTl + 1 * HID * HID, HID, HID, 0, 0);
    transpose_split_k<<<gtw, tblk>>>(Wv, WTh + 2 * HID * HID, WTl + 2 * HID * HID, HID, HID, 0, 0);

    // 2) merged QKV projection: M=16384, N=1536, K=512
    //    n<512 -> Q hi only, n<1024 -> K hi/lo, else V fp32
    dim3 g1((3 * HID) / 256, (BATCH * SEQ) / 128, 1);
    tgemm<4><<<g1, gblk, TGEMM_SMEM>>>(
        Xh, WTh, WTl, bq, bk, bv,
        Vp, Qh, Kh, Kl,
        HID, HID, HID, HID, 0, 0, 0, 1.f);

    // 3) transpose+split V: [seq][hid] -> plane[hid][seq], per batch
    dim3 gtv(HID / 32, SEQ / 32, BATCH);
    transpose_split_k<<<gtv, tblk>>>(Vp, VTh, VTl, SEQ, HID,
                                     (long long)SEQ * HID, (long long)HID * SEQ);

    // 4) scores = scale * Q @ K^T
    dim3 g2(SEQ / 256, SEQ / 128, BATCH);
    tgemm<1><<<g2, gblk, TGEMM_SMEM>>>(
        Qh, Kh, Kl, nullptr, nullptr, nullptr,
        Sp, nullptr, nullptr, nullptr,
        HID, HID, HID, SEQ,
        (long long)SEQ * HID, (long long)SEQ * HID, (long long)SEQ * SEQ, scale);

    // 5) softmax -> fp16 hi plane only (A-side)
    softmax_hi_k<<<BATCH * SEQ, 256>>>(Sp, Ph);

    // 6) out = P @ V
    dim3 g3(HID / 256, SEQ / 128, BATCH);
    tgemm<3><<<g3, gblk, TGEMM_SMEM>>>(
        Ph, VTh, VTl, nullptr, nullptr, nullptr,
        out, nullptr, nullptr, nullptr,
        SEQ, SEQ, SEQ, HID,
        (long long)SEQ * SEQ, (long long)HID * SEQ, (long long)SEQ * HID, 1.f);
}

// round 16
// speedup vs baseline: 2.2476x; 1.6863x over previous
// R16 = pure 1-pass fp16 GEMM (drop all lo planes).
// Measured one-sided split error was 1.35e-4; two-sided predicted ~2-3e-4 < 1e-3.
// MMA work halves vs R15; B fills halve; Kl/WTl/VTl planes removed.
#include <cuda_runtime.h>
#include <cuda_fp16.h>
#include <cstdint>

typedef unsigned int u32;
typedef unsigned long long u64;

#define BATCH 4
#define SEQ   4096
#define HID   512

// ---------------- scratch (no allocations allowed) ----------------
__device__ float g_V[BATCH * SEQ * HID];                    // fp32 V (pre-transpose)
__device__ float g_S[(size_t)BATCH * SEQ * SEQ];            // fp32 scores, 268 MB
__device__ __half g_Xh[BATCH * SEQ * HID];                  // X fp16 [seq][hid]
__device__ __half g_Qh[BATCH * SEQ * HID];                  // Q fp16
__device__ __half g_Kh[BATCH * SEQ * HID];                  // K fp16
__device__ __half g_Ph[(size_t)BATCH * SEQ * SEQ];          // P fp16, 134 MB
__device__ __half g_WTh[3 * HID * HID];                     // W^T fp16 [out][in], QKV stacked
__device__ __half g_VTh[BATCH * HID * SEQ];                 // V^T fp16 [hid][seq]

// ---------------- helpers ----------------
__device__ __forceinline__ u32 smem_u32(const void* p) {
    u32 a;
    asm("{ .reg .u64 t; cvta.to.shared.u64 t, %1; cvt.u32.u64 %0, t; }" : "=r"(a) : "l"(p));
    return a;
}

#define SW128(o) ((o) ^ (((o) >> 3) & 0x70))

#define CP16(dst, src) \
    asm volatile("cp.async.cg.shared.global [%0], [%1], 16;" :: "r"(dst), "l"(src) : "memory")
#define CP_COMMIT() asm volatile("cp.async.commit_group;" ::: "memory")
#define CP_WAIT0()  asm volatile("cp.async.wait_group 0;" ::: "memory")

__device__ __forceinline__ u32 pack_h2(__half a, __half b) {
    return (u32)__half_as_ushort(a) | ((u32)__half_as_ushort(b) << 16);
}

__device__ __forceinline__ void ldm4(u32& r0, u32& r1, u32& r2, u32& r3, u32 addr) {
    asm volatile("ldmatrix.sync.aligned.m8n8.x4.shared.b16 {%0,%1,%2,%3}, [%4];"
                 : "=r"(r0), "=r"(r1), "=r"(r2), "=r"(r3) : "r"(addr));
}

__device__ __forceinline__ void mma_f16(float* d, const u32* a, u32 b0, u32 b1) {
    asm volatile(
        "mma.sync.aligned.m16n8k16.row.col.f32.f16.f16.f32 "
        "{%0,%1,%2,%3}, {%4,%5,%6,%7}, {%8,%9}, {%0,%1,%2,%3};"
        : "+f"(d[0]), "+f"(d[1]), "+f"(d[2]), "+f"(d[3])
        : "r"(a[0]), "r"(a[1]), "r"(a[2]), "r"(a[3]), "r"(b0), "r"(b1));
}

// ---------------- HMMA fp16 1-pass GEMM ----------------
// D[M,N] = A[M,K] @ B[N,K]^T, plain fp16 x fp16 -> fp32 accumulate.
// CTA tile 128x256, K-chunk 64 (SW128 128B rows), double-buffered cp.async.
// 512 threads = 16 warps in 4(m) x 4(n); warp tile 32x64.
// Buffer (48 KB): A 16K | B 32K
// EPI: 1 = fp32 * scale, 3 = fp32, 4 = merged-QKV (Q fp16+bias, K fp16+bias, V fp32+bias)
static constexpr int BUF_BYTES = 49152;
static constexpr int TGEMM_SMEM = 1024 + 2 * BUF_BYTES;   // ~97 KB

template <int EPI>
__global__ __launch_bounds__(512, 1) void tgemm(
    const __half* __restrict__ Ah,
    const __half* __restrict__ Bh,
    const float* __restrict__ bias,  const float* __restrict__ bias2,
    const float* __restrict__ bias3,
    float* __restrict__ Cf,
    __half* __restrict__ Cqh,                 // EPI4: Q fp16
    __half* __restrict__ Ckh,                 // EPI4: K fp16
    int Kdim, int lda, int ldb, int ldc,
    long long sA, long long sB, long long sC, float scale)
{
    extern __shared__ char dsm[];

    const int tid = threadIdx.x;
    const long long z = blockIdx.z;
    const int m0 = blockIdx.y * 128, n0 = blockIdx.x * 256;

    const u32 dynb = smem_u32(dsm);
    const u32 pad = (1024u - (dynb & 1023u)) & 1023u;
    const u32 tbu = dynb + pad;

    // ---- cp.async fill: A 16KB + B 32KB; 6 x CP16/thread ----
    const int afr = tid >> 2;               // A row 0..127
    const int acb = (tid & 3) * 32;         // A byte offset in 128B row
    const int bfr = tid >> 1;               // B row 0..255
    const int bcb = (tid & 1) * 64;         // B byte offset in 128B row

    auto fill = [&](int t, int buf) {
        const int k0 = t * 64;
        const u32 base = tbu + (u32)buf * BUF_BYTES;
        {
            const char* ga = (const char*)(Ah + (size_t)z * sA + (size_t)(m0 + afr) * lda + k0) + acb;
            const u32 so0 = SW128((u32)(afr * 128 + acb));
            const u32 so1 = SW128((u32)(afr * 128 + acb + 16));
            CP16(base + so0, ga);
            CP16(base + so1, ga + 16);
        }
        {
            const char* gb = (const char*)(Bh + (size_t)z * sB + (size_t)(n0 + bfr) * ldb + k0) + bcb;
#pragma unroll
            for (int i = 0; i < 4; ++i) {
                const u32 so = SW128((u32)(bfr * 128 + bcb + i * 16));
                CP16(base + 16384 + so, gb + i * 16);
            }
        }
    };

    // ---- warp / lane geometry: 16 warps as 4(m) x 4(n), warp tile 32x64 ----
    const int lane = tid & 31;
    const int w = tid >> 5;
    const int wm = (w & 3) * 32;
    const int wn = (w >> 2) * 64;
    const int arow = (((lane >> 3) & 1) << 3) + (lane & 7);   // A: m within 16x16 tile
    const int akof = (lane >> 4) << 3;                        // A: k offset
    const int brow = ((lane >> 4) << 3) + (lane & 7);         // B: n within 16-col pair
    const int bkof = ((lane >> 3) & 1) << 3;                  // B: k offset

    float acc[2][8][4];
#pragma unroll
    for (int mt = 0; mt < 2; ++mt)
#pragma unroll
        for (int nt = 0; nt < 8; ++nt)
#pragma unroll
            for (int i = 0; i < 4; ++i) acc[mt][nt][i] = 0.f;

    auto compute = [&](int buf) {
        const u32 a_b = tbu + (u32)buf * BUF_BYTES;
        const u32 b_b = a_b + 16384;
#pragma unroll
        for (int ks = 0; ks < 4; ++ks) {
            const int kk = ks * 16;
            u32 Af[2][4];
#pragma unroll
            for (int mt = 0; mt < 2; ++mt) {
                const u32 off = SW128((u32)((wm + mt * 16 + arow) * 128 + (kk + akof) * 2));
                ldm4(Af[mt][0], Af[mt][1], Af[mt][2], Af[mt][3], a_b + off);
            }
#pragma unroll
            for (int npp = 0; npp < 2; ++npp) {
                u32 BH[2][4];
#pragma unroll
                for (int j = 0; j < 2; ++j) {
                    const int np = npp * 2 + j;
                    const u32 off = SW128((u32)((wn + np * 16 + brow) * 128 + (kk + bkof) * 2));
                    ldm4(BH[j][0], BH[j][1], BH[j][2], BH[j][3], b_b + off);
                }
#pragma unroll
                for (int j = 0; j < 2; ++j) {
                    const int np = npp * 2 + j;
#pragma unroll
                    for (int mt = 0; mt < 2; ++mt) {
                        mma_f16(acc[mt][np * 2 + 0], Af[mt], BH[j][0], BH[j][1]);
                        mma_f16(acc[mt][np * 2 + 1], Af[mt], BH[j][2], BH[j][3]);
                    }
                }
            }
        }
    };

    fill(0, 0);
    CP_COMMIT();
    CP_WAIT0();
    __syncthreads();

    const int nT = Kdim >> 6;
    int cur = 0;
    for (int t = 0; t < nT; ++t) {
        if (t + 1 < nT) { fill(t + 1, cur ^ 1); CP_COMMIT(); }
        compute(cur);
        if (t + 1 < nT) CP_WAIT0();
        __syncthreads();
        cur ^= 1;
    }

    // ---- epilogue: registers -> global ----
#pragma unroll
    for (int mt = 0; mt < 2; ++mt) {
#pragma unroll
        for (int nt = 0; nt < 8; ++nt) {
            const int mr = m0 + wm + mt * 16 + (lane >> 2);
            const int nc = n0 + wn + nt * 8 + (lane & 3) * 2;
            float v0 = acc[mt][nt][0], v1 = acc[mt][nt][1];
            float v2 = acc[mt][nt][2], v3 = acc[mt][nt][3];
            if (EPI == 1) { v0 *= scale; v1 *= scale; v2 *= scale; v3 *= scale; }
            if (EPI == 1 || EPI == 3) {
                float* c0 = Cf + (size_t)z * sC + (size_t)mr * ldc + nc;
                float* c1 = Cf + (size_t)z * sC + (size_t)(mr + 8) * ldc + nc;
                *(float2*)c0 = make_float2(v0, v1);
                *(float2*)c1 = make_float2(v2, v3);
            }
            if (EPI == 4) {
                const int nloc = nc & 511;
                const float* bp = (nc < 512) ? bias : (nc < 1024) ? bias2 : bias3;
                const float b0 = bp[nloc], b1 = bp[nloc + 1];
                v0 += b0; v1 += b1; v2 += b0; v3 += b1;
                const size_t o0 = (size_t)mr * HID + nloc;
                const size_t o1 = (size_t)(mr + 8) * HID + nloc;
                if (nc < 512) {
                    *(u32*)(Cqh + o0) = pack_h2(__float2half_rn(v0), __float2half_rn(v1));
                    *(u32*)(Cqh + o1) = pack_h2(__float2half_rn(v2), __float2half_rn(v3));
                } else if (nc < 1024) {
                    *(u32*)(Ckh + o0) = pack_h2(__float2half_rn(v0), __float2half_rn(v1));
                    *(u32*)(Ckh + o1) = pack_h2(__float2half_rn(v2), __float2half_rn(v3));
                } else {
                    *(float2*)(Cf + o0) = make_float2(v0, v1);
                    *(float2*)(Cf + o1) = make_float2(v2, v3);
                }
            }
        }
    }
}

// ---------------- elementwise fp16 convert: X -> Xh ----------------
__global__ __launch_bounds__(256) void split_hi_k(
    const float* __restrict__ in, __half* __restrict__ oh)
{
    const size_t i = ((size_t)blockIdx.x * 256 + threadIdx.x) * 4;
    float4 v = *(const float4*)(in + i);
    uint2 hp;
    hp.x = pack_h2(__float2half_rn(v.x), __float2half_rn(v.y));
    hp.y = pack_h2(__float2half_rn(v.z), __float2half_rn(v.w));
    *(uint2*)(oh + i) = hp;
}

// ---------------- transpose + fp16 convert: out[c][r] = h(in[r][c]) ----------------
__global__ __launch_bounds__(256) void transpose_hi_k(
    const float* __restrict__ in, __half* __restrict__ oh,
    int R, int C, long long sIn, long long sOut)
{
    __shared__ float tile[32][33];
    const long long z = blockIdx.z;
    in += z * sIn; oh += z * sOut;
    const int c0 = blockIdx.x * 32, r0 = blockIdx.y * 32;
    const int tx = threadIdx.x, ty = threadIdx.y;
#pragma unroll
    for (int j = 0; j < 32; j += 8)
        tile[ty + j][tx] = in[(size_t)(r0 + ty + j) * C + c0 + tx];
    __syncthreads();
#pragma unroll
    for (int j = 0; j < 32; j += 8) {
        float f = tile[tx][ty + j];
        oh[(size_t)(c0 + ty + j) * R + r0 + tx] = __float2half_rn(f);
    }
}

// ---------------- row softmax over 4096 cols, output fp16 plane ----------------
__global__ __launch_bounds__(256) void softmax_hi_k(
    const float* __restrict__ S, __half* __restrict__ Ph)
{
    const size_t row = blockIdx.x;
    const float4* p = reinterpret_cast<const float4*>(S + (row << 12));
    uint2* oh = reinterpret_cast<uint2*>(Ph + (row << 12));
    const int tid = threadIdx.x;

    float4 v[4];
#pragma unroll
    for (int r = 0; r < 4; ++r) v[r] = p[tid + (r << 8)];

    float m = v[0].x;
#pragma unroll
    for (int r = 0; r < 4; ++r) {
        m = fmaxf(m, v[r].x); m = fmaxf(m, v[r].y);
        m = fmaxf(m, v[r].z); m = fmaxf(m, v[r].w);
    }
#pragma unroll
    for (int o = 16; o > 0; o >>= 1) m = fmaxf(m, __shfl_xor_sync(0xffffffffu, m, o));

    __shared__ float red[8];
    if ((tid & 31) == 0) red[tid >> 5] = m;
    __syncthreads();
    m = red[0];
#pragma unroll
    for (int i = 1; i < 8; ++i) m = fmaxf(m, red[i]);
    __syncthreads();

    float s = 0.f;
#pragma unroll
    for (int r = 0; r < 4; ++r) {
        v[r].x = __expf(v[r].x - m); s += v[r].x;
        v[r].y = __expf(v[r].y - m); s += v[r].y;
        v[r].z = __expf(v[r].z - m); s += v[r].z;
        v[r].w = __expf(v[r].w - m); s += v[r].w;
    }
#pragma unroll
    for (int o = 16; o > 0; o >>= 1) s += __shfl_xor_sync(0xffffffffu, s, o);
    if ((tid & 31) == 0) red[tid >> 5] = s;
    __syncthreads();
    s = 0.f;
#pragma unroll
    for (int i = 0; i < 8; ++i) s += red[i];

    const float inv = 1.0f / s;
#pragma unroll
    for (int r = 0; r < 4; ++r) {
        uint2 hp;
        hp.x = pack_h2(__float2half_rn(v[r].x * inv), __float2half_rn(v[r].y * inv));
        hp.y = pack_h2(__float2half_rn(v[r].z * inv), __float2half_rn(v[r].w * inv));
        oh[tid + (r << 8)] = hp;
    }
}

// ---------------- launch ----------------
extern "C" void kernel_launch(void* const* d_in, const int* in_sizes, int n_in,
                              void* d_out, int out_size)
{
    (void)in_sizes; (void)n_in; (void)out_size;
    const float* X  = (const float*)d_in[0];
    const float* Wq = (const float*)d_in[1];
    const float* bq = (const float*)d_in[2];
    const float* Wk = (const float*)d_in[3];
    const float* bk = (const float*)d_in[4];
    const float* Wv = (const float*)d_in[5];
    const float* bv = (const float*)d_in[6];
    float* out = (float*)d_out;

    float *Vp, *Sp;
    __half *Xh, *Qh, *Kh, *Ph, *WTh, *VTh;
    cudaGetSymbolAddress((void**)&Vp,  g_V);
    cudaGetSymbolAddress((void**)&Sp,  g_S);
    cudaGetSymbolAddress((void**)&Xh,  g_Xh);
    cudaGetSymbolAddress((void**)&Qh,  g_Qh);
    cudaGetSymbolAddress((void**)&Kh,  g_Kh);
    cudaGetSymbolAddress((void**)&Ph,  g_Ph);
    cudaGetSymbolAddress((void**)&WTh, g_WTh);
    cudaGetSymbolAddress((void**)&VTh, g_VTh);

    cudaFuncSetAttribute(tgemm<1>, cudaFuncAttributeMaxDynamicSharedMemorySize, TGEMM_SMEM);
    cudaFuncSetAttribute(tgemm<3>, cudaFuncAttributeMaxDynamicSharedMemorySize, TGEMM_SMEM);
    cudaFuncSetAttribute(tgemm<4>, cudaFuncAttributeMaxDynamicSharedMemorySize, TGEMM_SMEM);

    const float scale = 0.04419417382415922f;  // 1/sqrt(512)
    dim3 gblk(512);
    dim3 tblk(32, 8);

    // 1a) X -> fp16
    split_hi_k<<<(BATCH * SEQ * HID) / (256 * 4), 256>>>(X, Xh);

    // 1b) transpose+convert weights: W[in][out] -> fp16 [out][in], QKV stacked
    dim3 gtw(HID / 32, HID / 32, 1);
    transpose_hi_k<<<gtw, tblk>>>(Wq, WTh + 0 * HID * HID, HID, HID, 0, 0);
    transpose_hi_k<<<gtw, tblk>>>(Wk, WTh + 1 * HID * HID, HID, HID, 0, 0);
    transpose_hi_k<<<gtw, tblk>>>(Wv, WTh + 2 * HID * HID, HID, HID, 0, 0);

    // 2) merged QKV projection: M=16384, N=1536, K=512
    //    n<512 -> Q fp16, n<1024 -> K fp16, else V fp32
    dim3 g1((3 * HID) / 256, (BATCH * SEQ) / 128, 1);
    tgemm<4><<<g1, gblk, TGEMM_SMEM>>>(
        Xh, WTh, bq, bk, bv,
        Vp, Qh, Kh,
        HID, HID, HID, HID, 0, 0, 0, 1.f);

    // 3) transpose+convert V: [seq][hid] -> fp16 [hid][seq], per batch
    dim3 gtv(HID / 32, SEQ / 32, BATCH);
    transpose_hi_k<<<gtv, tblk>>>(Vp, VTh, SEQ, HID,
                                  (long long)SEQ * HID, (long long)HID * SEQ);

    // 4) scores = scale * Q @ K^T
    dim3 g2(SEQ / 256, SEQ / 128, BATCH);
    tgemm<1><<<g2, gblk, TGEMM_SMEM>>>(
        Qh, Kh, nullptr, nullptr, nullptr,
        Sp, nullptr, nullptr,
        HID, HID, HID, SEQ,
        (long long)SEQ * HID, (long long)SEQ * HID, (long long)SEQ * SEQ, scale);

    // 5) softmax -> fp16 plane
    softmax_hi_k<<<BATCH * SEQ, 256>>>(Sp, Ph);

    // 6) out = P @ V
    dim3 g3(HID / 256, SEQ / 128, BATCH);
    tgemm<3><<<g3, gblk, TGEMM_SMEM>>>(
        Ph, VTh, nullptr, nullptr, nullptr,
        out, nullptr, nullptr,
        SEQ, SEQ, SEQ, HID,
        (long long)SEQ * SEQ, (long long)HID * SEQ, (long long)SEQ * HID, 1.f);
}

// round 17
// speedup vs baseline: 2.3734x; 1.0560x over previous
// R17 = R16 + (a) unnormalized-exp fusion: GEMM2 epilogue writes fp16 exp(S)
// + atomic row-sums Z; GEMM3 epilogue divides by Z -> softmax kernel and fp32 S
// eliminated. (b) K-chunk 128 (two 64-k subtiles), halving barrier count.
#include <cuda_runtime.h>
#include <cuda_fp16.h>
#include <cstdint>

typedef unsigned int u32;
typedef unsigned long long u64;

#define BATCH 4
#define SEQ   4096
#define HID   512

// ---------------- scratch (no allocations allowed) ----------------
__device__ float g_V[BATCH * SEQ * HID];                    // fp32 V (pre-transpose)
__device__ float g_Z[BATCH * SEQ];                          // softmax row sums
__device__ __half g_Xh[BATCH * SEQ * HID];                  // X fp16 [seq][hid]
__device__ __half g_Qh[BATCH * SEQ * HID];                  // Q fp16
__device__ __half g_Kh[BATCH * SEQ * HID];                  // K fp16
__device__ __half g_Ph[(size_t)BATCH * SEQ * SEQ];          // exp(S) fp16, 134 MB
__device__ __half g_WTh[3 * HID * HID];                     // W^T fp16 [out][in], QKV stacked
__device__ __half g_VTh[BATCH * HID * SEQ];                 // V^T fp16 [hid][seq]

// ---------------- helpers ----------------
__device__ __forceinline__ u32 smem_u32(const void* p) {
    u32 a;
    asm("{ .reg .u64 t; cvta.to.shared.u64 t, %1; cvt.u32.u64 %0, t; }" : "=r"(a) : "l"(p));
    return a;
}

#define SW128(o) ((o) ^ (((o) >> 3) & 0x70))

#define CP16(dst, src) \
    asm volatile("cp.async.cg.shared.global [%0], [%1], 16;" :: "r"(dst), "l"(src) : "memory")
#define CP_COMMIT() asm volatile("cp.async.commit_group;" ::: "memory")
#define CP_WAIT0()  asm volatile("cp.async.wait_group 0;" ::: "memory")

__device__ __forceinline__ u32 pack_h2(__half a, __half b) {
    return (u32)__half_as_ushort(a) | ((u32)__half_as_ushort(b) << 16);
}

__device__ __forceinline__ void ldm4(u32& r0, u32& r1, u32& r2, u32& r3, u32 addr) {
    asm volatile("ldmatrix.sync.aligned.m8n8.x4.shared.b16 {%0,%1,%2,%3}, [%4];"
                 : "=r"(r0), "=r"(r1), "=r"(r2), "=r"(r3) : "r"(addr));
}

__device__ __forceinline__ void mma_f16(float* d, const u32* a, u32 b0, u32 b1) {
    asm volatile(
        "mma.sync.aligned.m16n8k16.row.col.f32.f16.f16.f32 "
        "{%0,%1,%2,%3}, {%4,%5,%6,%7}, {%8,%9}, {%0,%1,%2,%3};"
        : "+f"(d[0]), "+f"(d[1]), "+f"(d[2]), "+f"(d[3])
        : "r"(a[0]), "r"(a[1]), "r"(a[2]), "r"(a[3]), "r"(b0), "r"(b1));
}

// ---------------- HMMA fp16 GEMM ----------------
// D[M,N] = A[M,K] @ B[N,K]^T, fp16 x fp16 -> fp32 accumulate.
// CTA tile 128x256, K-chunk 128 as two 64-k SW128 subtiles, double-buffered.
// 512 threads = 16 warps in 4(m) x 4(n); warp tile 32x64.
// Buffer (96 KB): A0 16K | A1 16K | B0 32K | B1 32K
// EPI: 4 = merged-QKV (Q fp16+bias, K fp16+bias, V fp32+bias)
//      5 = exp-scores: Ph = fp16 exp(scale*s), atomic row sums into Zg
//      6 = PV: fp32 out divided by Zg[row]
static constexpr int BUF_BYTES = 98304;
static constexpr int TGEMM_SMEM = 1024 + 2 * BUF_BYTES;   // ~193 KB

template <int EPI>
__global__ __launch_bounds__(512, 1) void tgemm(
    const __half* __restrict__ Ah,
    const __half* __restrict__ Bh,
    const float* __restrict__ bias,  const float* __restrict__ bias2,
    const float* __restrict__ bias3,
    float* __restrict__ Cf,
    __half* __restrict__ Cqh,                 // EPI4: Q fp16 / EPI5: Ph target
    __half* __restrict__ Ckh,                 // EPI4: K fp16
    float* __restrict__ Zg,                   // EPI5: atomic sums / EPI6: read
    int Kdim, int lda, int ldb, int ldc,
    long long sA, long long sB, long long sC, float scale)
{
    extern __shared__ char dsm[];

    const int tid = threadIdx.x;
    const long long z = blockIdx.z;
    const int m0 = blockIdx.y * 128, n0 = blockIdx.x * 256;

    const u32 dynb = smem_u32(dsm);
    const u32 pad = (1024u - (dynb & 1023u)) & 1023u;
    const u32 tbu = dynb + pad;

    // ---- cp.async fill: per buffer A 2x16KB + B 2x32KB; 12 x CP16/thread ----
    const int afr = tid >> 2;               // A row 0..127
    const int acb = (tid & 3) * 32;         // A byte offset in 128B subtile row
    const int bfr = tid >> 1;               // B row 0..255
    const int bcb = (tid & 1) * 64;         // B byte offset in 128B subtile row

    auto fill = [&](int t, int buf) {
        const int k0 = t * 128;
        const u32 base = tbu + (u32)buf * BUF_BYTES;
#pragma unroll
        for (int s = 0; s < 2; ++s) {
            const char* ga = (const char*)(Ah + (size_t)z * sA + (size_t)(m0 + afr) * lda + k0 + s * 64) + acb;
            const u32 so0 = SW128((u32)(afr * 128 + acb));
            const u32 so1 = SW128((u32)(afr * 128 + acb + 16));
            CP16(base + (u32)s * 16384 + so0, ga);
            CP16(base + (u32)s * 16384 + so1, ga + 16);
            const char* gb = (const char*)(Bh + (size_t)z * sB + (size_t)(n0 + bfr) * ldb + k0 + s * 64) + bcb;
#pragma unroll
            for (int i = 0; i < 4; ++i) {
                const u32 so = SW128((u32)(bfr * 128 + bcb + i * 16));
                CP16(base + 32768 + (u32)s * 32768 + so, gb + i * 16);
            }
        }
    };

    // ---- warp / lane geometry: 16 warps as 4(m) x 4(n), warp tile 32x64 ----
    const int lane = tid & 31;
    const int w = tid >> 5;
    const int wm = (w & 3) * 32;
    const int wn = (w >> 2) * 64;
    const int arow = (((lane >> 3) & 1) << 3) + (lane & 7);
    const int akof = (lane >> 4) << 3;
    const int brow = ((lane >> 4) << 3) + (lane & 7);
    const int bkof = ((lane >> 3) & 1) << 3;

    float acc[2][8][4];
#pragma unroll
    for (int mt = 0; mt < 2; ++mt)
#pragma unroll
        for (int nt = 0; nt < 8; ++nt)
#pragma unroll
            for (int i = 0; i < 4; ++i) acc[mt][nt][i] = 0.f;

    auto compute = [&](int buf) {
        const u32 base = tbu + (u32)buf * BUF_BYTES;
#pragma unroll
        for (int s = 0; s < 2; ++s) {
            const u32 a_b = base + (u32)s * 16384;
            const u32 b_b = base + 32768 + (u32)s * 32768;
#pragma unroll
            for (int ks = 0; ks < 4; ++ks) {
                const int kk = ks * 16;
                u32 Af[2][4];
#pragma unroll
                for (int mt = 0; mt < 2; ++mt) {
                    const u32 off = SW128((u32)((wm + mt * 16 + arow) * 128 + (kk + akof) * 2));
                    ldm4(Af[mt][0], Af[mt][1], Af[mt][2], Af[mt][3], a_b + off);
                }
#pragma unroll
                for (int npp = 0; npp < 2; ++npp) {
                    u32 BF[2][4];
#pragma unroll
                    for (int j = 0; j < 2; ++j) {
                        const int np = npp * 2 + j;
                        const u32 off = SW128((u32)((wn + np * 16 + brow) * 128 + (kk + bkof) * 2));
                        ldm4(BF[j][0], BF[j][1], BF[j][2], BF[j][3], b_b + off);
                    }
#pragma unroll
                    for (int j = 0; j < 2; ++j) {
                        const int np = npp * 2 + j;
#pragma unroll
                        for (int mt = 0; mt < 2; ++mt) {
                            mma_f16(acc[mt][np * 2 + 0], Af[mt], BF[j][0], BF[j][1]);
                            mma_f16(acc[mt][np * 2 + 1], Af[mt], BF[j][2], BF[j][3]);
                        }
                    }
                }
            }
        }
    };

    fill(0, 0);
    CP_COMMIT();
    CP_WAIT0();
    __syncthreads();

    const int nT = Kdim >> 7;
    int cur = 0;
    for (int t = 0; t < nT; ++t) {
        if (t + 1 < nT) { fill(t + 1, cur ^ 1); CP_COMMIT(); }
        compute(cur);
        if (t + 1 < nT) CP_WAIT0();
        __syncthreads();
        cur ^= 1;
    }

    // ---- epilogue ----
#pragma unroll
    for (int mt = 0; mt < 2; ++mt) {
        float rs0 = 0.f, rs1 = 0.f;   // EPI5 row sums
#pragma unroll
        for (int nt = 0; nt < 8; ++nt) {
            const int mr = m0 + wm + mt * 16 + (lane >> 2);
            const int nc = n0 + wn + nt * 8 + (lane & 3) * 2;
            float v0 = acc[mt][nt][0], v1 = acc[mt][nt][1];
            float v2 = acc[mt][nt][2], v3 = acc[mt][nt][3];
            if (EPI == 5) {
                v0 = __expf(v0 * scale); v1 = __expf(v1 * scale);
                v2 = __expf(v2 * scale); v3 = __expf(v3 * scale);
                rs0 += v0 + v1;
                rs1 += v2 + v3;
                __half* ph = Cqh + (size_t)z * sC;
                *(u32*)(ph + (size_t)mr * ldc + nc)       = pack_h2(__float2half_rn(v0), __float2half_rn(v1));
                *(u32*)(ph + (size_t)(mr + 8) * ldc + nc) = pack_h2(__float2half_rn(v2), __float2half_rn(v3));
            }
            if (EPI == 6) {
                const float z0 = Zg[z * SEQ + mr];
                const float z1 = Zg[z * SEQ + mr + 8];
                v0 /= z0; v1 /= z0; v2 /= z1; v3 /= z1;
                float* c0 = Cf + (size_t)z * sC + (size_t)mr * ldc + nc;
                float* c1 = Cf + (size_t)z * sC + (size_t)(mr + 8) * ldc + nc;
                *(float2*)c0 = make_float2(v0, v1);
                *(float2*)c1 = make_float2(v2, v3);
            }
            if (EPI == 4) {
                const int nloc = nc & 511;
                const float* bp = (nc < 512) ? bias : (nc < 1024) ? bias2 : bias3;
                const float b0 = bp[nloc], b1 = bp[nloc + 1];
                v0 += b0; v1 += b1; v2 += b0; v3 += b1;
                const size_t o0 = (size_t)mr * HID + nloc;
                const size_t o1 = (size_t)(mr + 8) * HID + nloc;
                if (nc < 512) {
                    *(u32*)(Cqh + o0) = pack_h2(__float2half_rn(v0), __float2half_rn(v1));
                    *(u32*)(Cqh + o1) = pack_h2(__float2half_rn(v2), __float2half_rn(v3));
                } else if (nc < 1024) {
                    *(u32*)(Ckh + o0) = pack_h2(__float2half_rn(v0), __float2half_rn(v1));
                    *(u32*)(Ckh + o1) = pack_h2(__float2half_rn(v2), __float2half_rn(v3));
                } else {
                    *(float2*)(Cf + o0) = make_float2(v0, v1);
                    *(float2*)(Cf + o1) = make_float2(v2, v3);
                }
            }
        }
        if (EPI == 5) {
            // reduce over the 4 lanes sharing these rows (lane bits 0..1)
            rs0 += __shfl_xor_sync(0xffffffffu, rs0, 1);
            rs0 += __shfl_xor_sync(0xffffffffu, rs0, 2);
            rs1 += __shfl_xor_sync(0xffffffffu, rs1, 1);
            rs1 += __shfl_xor_sync(0xffffffffu, rs1, 2);
            if ((lane & 3) == 0) {
                const int mr = m0 + wm + mt * 16 + (lane >> 2);
                atomicAdd(Zg + z * SEQ + mr, rs0);
                atomicAdd(Zg + z * SEQ + mr + 8, rs1);
            }
        }
    }
}

// ---------------- zero the Z array ----------------
__global__ __launch_bounds__(256) void zero_k(float* __restrict__ Zg)
{
    Zg[blockIdx.x * 256 + threadIdx.x] = 0.f;
}

// ---------------- elementwise fp16 convert: X -> Xh ----------------
__global__ __launch_bounds__(256) void split_hi_k(
    const float* __restrict__ in, __half* __restrict__ oh)
{
    const size_t i = ((size_t)blockIdx.x * 256 + threadIdx.x) * 4;
    float4 v = *(const float4*)(in + i);
    uint2 hp;
    hp.x = pack_h2(__float2half_rn(v.x), __float2half_rn(v.y));
    hp.y = pack_h2(__float2half_rn(v.z), __float2half_rn(v.w));
    *(uint2*)(oh + i) = hp;
}

// ---------------- transpose + fp16 convert: out[c][r] = h(in[r][c]) ----------------
__global__ __launch_bounds__(256) void transpose_hi_k(
    const float* __restrict__ in, __half* __restrict__ oh,
    int R, int C, long long sIn, long long sOut)
{
    __shared__ float tile[32][33];
    const long long z = blockIdx.z;
    in += z * sIn; oh += z * sOut;
    const int c0 = blockIdx.x * 32, r0 = blockIdx.y * 32;
    const int tx = threadIdx.x, ty = threadIdx.y;
#pragma unroll
    for (int j = 0; j < 32; j += 8)
        tile[ty + j][tx] = in[(size_t)(r0 + ty + j) * C + c0 + tx];
    __syncthreads();
#pragma unroll
    for (int j = 0; j < 32; j += 8) {
        float f = tile[tx][ty + j];
        oh[(size_t)(c0 + ty + j) * R + r0 + tx] = __float2half_rn(f);
    }
}

// ---------------- launch ----------------
extern "C" void kernel_launch(void* const* d_in, const int* in_sizes, int n_in,
                              void* d_out, int out_size)
{
    (void)in_sizes; (void)n_in; (void)out_size;
    const float* X  = (const float*)d_in[0];
    const float* Wq = (const float*)d_in[1];
    const float* bq = (const float*)d_in[2];
    const float* Wk = (const float*)d_in[3];
    const float* bk = (const float*)d_in[4];
    const float* Wv = (const float*)d_in[5];
    const float* bv = (const float*)d_in[6];
    float* out = (float*)d_out;

    float *Vp, *Zp;
    __half *Xh, *Qh, *Kh, *Ph, *WTh, *VTh;
    cudaGetSymbolAddress((void**)&Vp,  g_V);
    cudaGetSymbolAddress((void**)&Zp,  g_Z);
    cudaGetSymbolAddress((void**)&Xh,  g_Xh);
    cudaGetSymbolAddress((void**)&Qh,  g_Qh);
    cudaGetSymbolAddress((void**)&Kh,  g_Kh);
    cudaGetSymbolAddress((void**)&Ph,  g_Ph);
    cudaGetSymbolAddress((void**)&WTh, g_WTh);
    cudaGetSymbolAddress((void**)&VTh, g_VTh);

    cudaFuncSetAttribute(tgemm<4>, cudaFuncAttributeMaxDynamicSharedMemorySize, TGEMM_SMEM);
    cudaFuncSetAttribute(tgemm<5>, cudaFuncAttributeMaxDynamicSharedMemorySize, TGEMM_SMEM);
    cudaFuncSetAttribute(tgemm<6>, cudaFuncAttributeMaxDynamicSharedMemorySize, TGEMM_SMEM);

    const float scale = 0.04419417382415922f;  // 1/sqrt(512)
    dim3 gblk(512);
    dim3 tblk(32, 8);

    // 1a) X -> fp16
    split_hi_k<<<(BATCH * SEQ * HID) / (256 * 4), 256>>>(X, Xh);

    // 1b) transpose+convert weights: W[in][out] -> fp16 [out][in], QKV stacked
    dim3 gtw(HID / 32, HID / 32, 1);
    transpose_hi_k<<<gtw, tblk>>>(Wq, WTh + 0 * HID * HID, HID, HID, 0, 0);
    transpose_hi_k<<<gtw, tblk>>>(Wk, WTh + 1 * HID * HID, HID, HID, 0, 0);
    transpose_hi_k<<<gtw, tblk>>>(Wv, WTh + 2 * HID * HID, HID, HID, 0, 0);

    // 2) merged QKV projection: M=16384, N=1536, K=512
    dim3 g1((3 * HID) / 256, (BATCH * SEQ) / 128, 1);
    tgemm<4><<<g1, gblk, TGEMM_SMEM>>>(
        Xh, WTh, bq, bk, bv,
        Vp, Qh, Kh, nullptr,
        HID, HID, HID, HID, 0, 0, 0, 1.f);

    // 3) transpose+convert V: [seq][hid] -> fp16 [hid][seq], per batch
    dim3 gtv(HID / 32, SEQ / 32, BATCH);
    transpose_hi_k<<<gtv, tblk>>>(Vp, VTh, SEQ, HID,
                                  (long long)SEQ * HID, (long long)HID * SEQ);

    // 4) zero Z, then exp-scores: Ph = exp(scale * Q@K^T), Z = row sums
    zero_k<<<(BATCH * SEQ) / 256, 256>>>(Zp);
    dim3 g2(SEQ / 256, SEQ / 128, BATCH);
    tgemm<5><<<g2, gblk, TGEMM_SMEM>>>(
        Qh, Kh, nullptr, nullptr, nullptr,
        nullptr, Ph, nullptr, Zp,
        HID, HID, HID, SEQ,
        (long long)SEQ * HID, (long long)SEQ * HID, (long long)SEQ * SEQ, scale);

    // 5) out = (Ph @ V) / Z
    dim3 g3(HID / 256, SEQ / 128, BATCH);
    tgemm<6><<<g3, gblk, TGEMM_SMEM>>>(
        Ph, VTh, nullptr, nullptr, nullptr,
        out, nullptr, nullptr, Zp,
        SEQ, SEQ, SEQ, HID,
        (long long)SEQ * SEQ, (long long)HID * SEQ, (long long)SEQ * HID, 1.f);
}